// round 12
// baseline (speedup 1.0000x reference)
#include <cuda_runtime.h>
#include <math.h>

#define NI 4096
#define NH 8192
#define NO 2048

// ---------------- device scratch (allocation-free) ----------------
__device__ float g_base_h[NH];
__device__ float g_base_o[NO];
__device__ float g_act_a[NH];
__device__ float g_act_b[NH];
__device__ int   g_flags[3];   // [0]=activs0 nonzero, [1]=outputs0 nonzero, [2]=always 1

// ---------------- helpers ----------------
__device__ __forceinline__ float apply_act(float x, int id) {
    switch (id) {
        case 0:  return x;
        case 1:  return x >= 0.f ? x : 0.01f * x;
        case 2:  return fmaxf(x, 0.f);
        case 3:  return 1.f / (1.f + expf(-x));
        default: return tanhf(x);
    }
}

// Streaming (evict-first) float4 load for weight rows — keeps the 100s-of-MB
// weight streams from thrashing L2, protecting the reused x / base vectors.
__device__ __forceinline__ float4 ldcs4(const float4* p) {
    float4 v;
    asm volatile("ld.global.cs.v4.f32 {%0,%1,%2,%3}, [%4];"
                 : "=f"(v.x), "=f"(v.y), "=f"(v.z), "=f"(v.w) : "l"(p));
    return v;
}

// Per-warp dot(W_row, x); works for K in {2048, 4096, 8192}
// (n4 in {512,1024,2048}, stride 256, 8-way unroll).
__device__ __forceinline__ float warp_dot(const float* __restrict__ Wrow,
                                          const float* __restrict__ x,
                                          int K, int lane) {
    const float4* __restrict__ w4 = reinterpret_cast<const float4*>(Wrow);
    const float4* __restrict__ x4 = reinterpret_cast<const float4*>(x);
    const int n4 = K >> 2;
    float acc0 = 0.f, acc1 = 0.f, acc2 = 0.f, acc3 = 0.f;
    float acc4 = 0.f, acc5 = 0.f, acc6 = 0.f, acc7 = 0.f;
    for (int i = lane; i < n4; i += 256) {
        float4 a0 = ldcs4(w4 + i      ); float4 b0 = x4[i      ];
        float4 a1 = ldcs4(w4 + i +  32); float4 b1 = x4[i +  32];
        float4 a2 = ldcs4(w4 + i +  64); float4 b2 = x4[i +  64];
        float4 a3 = ldcs4(w4 + i +  96); float4 b3 = x4[i +  96];
        float4 a4 = ldcs4(w4 + i + 128); float4 b4 = x4[i + 128];
        float4 a5 = ldcs4(w4 + i + 160); float4 b5 = x4[i + 160];
        float4 a6 = ldcs4(w4 + i + 192); float4 b6 = x4[i + 192];
        float4 a7 = ldcs4(w4 + i + 224); float4 b7 = x4[i + 224];
        acc0 += a0.x*b0.x + a0.y*b0.y + a0.z*b0.z + a0.w*b0.w;
        acc1 += a1.x*b1.x + a1.y*b1.y + a1.z*b1.z + a1.w*b1.w;
        acc2 += a2.x*b2.x + a2.y*b2.y + a2.z*b2.z + a2.w*b2.w;
        acc3 += a3.x*b3.x + a3.y*b3.y + a3.z*b3.z + a3.w*b3.w;
        acc4 += a4.x*b4.x + a4.y*b4.y + a4.z*b4.z + a4.w*b4.w;
        acc5 += a5.x*b5.x + a5.y*b5.y + a5.z*b5.z + a5.w*b5.w;
        acc6 += a6.x*b6.x + a6.y*b6.y + a6.z*b6.z + a6.w*b6.w;
        acc7 += a7.x*b7.x + a7.y*b7.y + a7.z*b7.z + a7.w*b7.w;
    }
    return ((acc0 + acc1) + (acc2 + acc3)) + ((acc4 + acc5) + (acc6 + acc7));
}

__device__ __forceinline__ float warp_reduce(float s) {
    #pragma unroll
    for (int off = 16; off; off >>= 1)
        s += __shfl_xor_sync(0xffffffffu, s, off);
    return s;
}

// ---------------- kernels ----------------

__global__ void flag_kernel(const float* __restrict__ act0,
                            const float* __restrict__ out0) {
    const float* p = (blockIdx.x == 0) ? act0 : out0;
    const int    n = (blockIdx.x == 0) ? NH : NO;
    int any = 0;
    for (int i = threadIdx.x; i < n; i += blockDim.x)
        any |= (p[i] != 0.f);
    any = __syncthreads_or(any);
    if (threadIdx.x == 0) {
        g_flags[blockIdx.x] = any;
        g_flags[2] = 1;
    }
}

// Fused loop-invariant bases for hidden AND output rows in one launch.
// Blocks [0, NH/8): base_h rows. Blocks [NH/8, NH/8+NO/8): base_o rows.
// If activs0 is all-zero, also emits the step-1 result act_a directly.
__global__ void base_fused_kernel(
    const float* __restrict__ W_i2h, const float* __restrict__ W_o2h,
    const float* __restrict__ W_i2o, const float* __restrict__ W_o2o,
    const float* __restrict__ inputs, const float* __restrict__ outputs0,
    const float* __restrict__ h_resp, const float* __restrict__ h_bias,
    const int*   __restrict__ h_ids)
{
    const int warp = (blockIdx.x * blockDim.x + threadIdx.x) >> 5;
    const int lane = threadIdx.x & 31;
    const int out_flag = g_flags[1];

    if (warp < NH) {                    // hidden base row
        const int row = warp;
        float s = warp_dot(W_i2h + (size_t)row * NI, inputs, NI, lane);
        if (out_flag)
            s += warp_dot(W_o2h + (size_t)row * NO, outputs0, NO, lane);
        s = warp_reduce(s);
        if (lane == 0) {
            g_base_h[row] = s;
            if (!g_flags[0]) {          // activs0 == 0 -> step-1 result now
                float pre = h_resp[row] * s + h_bias[row];
                g_act_a[row] = apply_act(pre, h_ids[row]);
            }
        }
    } else {                            // output base row
        const int row = warp - NH;
        if (row >= NO) return;
        float s = warp_dot(W_i2o + (size_t)row * NI, inputs, NI, lane);
        if (out_flag)
            s += warp_dot(W_o2o + (size_t)row * NO, outputs0, NO, lane);
        s = warp_reduce(s);
        if (lane == 0) g_base_o[row] = s;
    }
}

// Step-1 hidden kernel: early-exit if activs0 was all-zero (act_a already
// written by base_fused_kernel); otherwise full GEMV + epilogue.
__global__ void step1_kernel(const float* __restrict__ W,
                             const float* __restrict__ activs0,
                             const float* __restrict__ resp,
                             const float* __restrict__ bias,
                             const int*   __restrict__ ids)
{
    if (!g_flags[0]) return;
    const int row  = (blockIdx.x * blockDim.x + threadIdx.x) >> 5;
    const int lane = threadIdx.x & 31;
    if (row >= NH) return;
    float s = warp_dot(W + (size_t)row * NH, activs0, NH, lane);
    s = warp_reduce(s);
    if (lane == 0) {
        float pre = resp[row] * (g_base_h[row] + s) + bias[row];
        g_act_a[row] = apply_act(pre, ids[row]);
    }
}

// Generic recurrent / output GEMV + activation epilogue.
__global__ void gemv_act_kernel(const float* __restrict__ W,
                                const float* __restrict__ x, int K,
                                const float* __restrict__ base,
                                const float* __restrict__ resp,
                                const float* __restrict__ bias,
                                const int*   __restrict__ ids,
                                float* __restrict__ y, int M)
{
    const int row  = (blockIdx.x * blockDim.x + threadIdx.x) >> 5;
    const int lane = threadIdx.x & 31;
    if (row >= M) return;
    float s = warp_dot(W + (size_t)row * K, x, K, lane);
    s = warp_reduce(s);
    if (lane == 0) {
        float pre = resp[row] * (base[row] + s) + bias[row];
        y[row] = apply_act(pre, ids[row]);
    }
}

// ---------------- launch ----------------
extern "C" void kernel_launch(void* const* d_in, const int* in_sizes, int n_in,
                              void* d_out, int out_size) {
    const float* inputs   = (const float*)d_in[0];
    const float* W_i2h    = (const float*)d_in[1];
    const float* W_h2h    = (const float*)d_in[2];
    const float* W_o2h    = (const float*)d_in[3];
    const float* W_i2o    = (const float*)d_in[4];
    const float* W_h2o    = (const float*)d_in[5];
    const float* W_o2o    = (const float*)d_in[6];
    const float* h_resp   = (const float*)d_in[7];
    const float* h_bias   = (const float*)d_in[8];
    const float* o_resp   = (const float*)d_in[9];
    const float* o_bias   = (const float*)d_in[10];
    const float* activs0  = (const float*)d_in[11];
    const float* outputs0 = (const float*)d_in[12];
    const int*   h_ids    = (const int*)d_in[13];
    const int*   o_ids    = (const int*)d_in[14];
    float* out = (float*)d_out;

    static float *base_h = nullptr, *base_o, *act_a, *act_b;
    if (!base_h) {
        cudaGetSymbolAddress((void**)&base_h, g_base_h);
        cudaGetSymbolAddress((void**)&base_o, g_base_o);
        cudaGetSymbolAddress((void**)&act_a,  g_act_a);
        cudaGetSymbolAddress((void**)&act_b,  g_act_b);
    }

    const int THREADS  = 256;                    // 8 warps = 8 rows / block
    const int BLK_NH   = NH / 8;                 // 1024
    const int BLK_NO   = NO / 8;                 // 256
    const int BLK_BASE = BLK_NH + BLK_NO;        // 1280

    // 0. zero-vector flags
    flag_kernel<<<2, THREADS>>>(activs0, outputs0);

    // 1. all loop-invariant bases in one launch (+ step-1 result if activs0==0)
    base_fused_kernel<<<BLK_BASE, THREADS>>>(W_i2h, W_o2h, W_i2o, W_o2o,
                                             inputs, outputs0,
                                             h_resp, h_bias, h_ids);

    // 2. recurrent steps
    step1_kernel<<<BLK_NH, THREADS>>>(W_h2h, activs0, h_resp, h_bias, h_ids);
    gemv_act_kernel<<<BLK_NH, THREADS>>>(W_h2h, act_a, NH, base_h,
                                         h_resp, h_bias, h_ids, act_b, NH);
    gemv_act_kernel<<<BLK_NH, THREADS>>>(W_h2h, act_b, NH, base_h,
                                         h_resp, h_bias, h_ids, act_a, NH);

    // 3. output layer
    gemv_act_kernel<<<BLK_NO, THREADS>>>(W_h2o, act_a, NH, base_o,
                                         o_resp, o_bias, o_ids, out, NO);
}

// round 16
// speedup vs baseline: 1.1609x; 1.1609x over previous
#include <cuda_runtime.h>
#include <math.h>

#define NI 4096
#define NH 8192
#define NO 2048

// ---------------- device scratch (allocation-free) ----------------
__device__ float g_base_h[NH];
__device__ float g_base_o[NO];
__device__ float g_act_a[NH];
__device__ float g_act_b[NH];
__device__ int   g_flags[3];   // [0]=activs0 nonzero, [1]=outputs0 nonzero, [2]=always 1

// ---------------- helpers ----------------
__device__ __forceinline__ float apply_act(float x, int id) {
    switch (id) {
        case 0:  return x;
        case 1:  return x >= 0.f ? x : 0.01f * x;
        case 2:  return fmaxf(x, 0.f);
        case 3:  return 1.f / (1.f + expf(-x));
        default: return tanhf(x);
    }
}

// Streaming (evict-first) float4 load for weight rows.
__device__ __forceinline__ float4 ldcs4(const float4* p) {
    float4 v;
    asm volatile("ld.global.cs.v4.f32 {%0,%1,%2,%3}, [%4];"
                 : "=f"(v.x), "=f"(v.y), "=f"(v.z), "=f"(v.w) : "l"(p));
    return v;
}

// Per-warp dot(W_row, x) with DOUBLE-BUFFERED prefetch.
// The next chunk's 4 float4 loads are issued at the top of the iteration but
// consumed only in the NEXT iteration — the data dependence forces ptxas to
// keep them live across the FMA body, guaranteeing ~4 outstanding DRAM misses
// per warp (R12 ncu showed regs=38: ptxas had sunk the plain 8-way unroll to
// MLP~2, capping BW at 4.9 TB/s).
// Valid for K in {2048, 4096, 8192}: n4 in {512,1024,2048}, chunk = 128 float4.
__device__ __forceinline__ float warp_dot(const float* __restrict__ Wrow,
                                          const float* __restrict__ x,
                                          int K, int lane) {
    const float4* __restrict__ w4 = reinterpret_cast<const float4*>(Wrow);
    const float4* __restrict__ x4 = reinterpret_cast<const float4*>(x);
    const int n4 = K >> 2;
    float acc0 = 0.f, acc1 = 0.f, acc2 = 0.f, acc3 = 0.f;

    // prime current buffer
    float4 c0 = ldcs4(w4 + lane);
    float4 c1 = ldcs4(w4 + lane + 32);
    float4 c2 = ldcs4(w4 + lane + 64);
    float4 c3 = ldcs4(w4 + lane + 96);

    int i = lane;
    #pragma unroll 1
    for (; i + 128 < n4; i += 128) {
        // prefetch next chunk (kept live across the FMAs below)
        float4 p0 = ldcs4(w4 + i + 128);
        float4 p1 = ldcs4(w4 + i + 160);
        float4 p2 = ldcs4(w4 + i + 192);
        float4 p3 = ldcs4(w4 + i + 224);
        // x loads (L1/L2-resident) + compute on current buffer
        float4 b0 = x4[i];      float4 b1 = x4[i + 32];
        float4 b2 = x4[i + 64]; float4 b3 = x4[i + 96];
        acc0 += c0.x*b0.x + c0.y*b0.y + c0.z*b0.z + c0.w*b0.w;
        acc1 += c1.x*b1.x + c1.y*b1.y + c1.z*b1.z + c1.w*b1.w;
        acc2 += c2.x*b2.x + c2.y*b2.y + c2.z*b2.z + c2.w*b2.w;
        acc3 += c3.x*b3.x + c3.y*b3.y + c3.z*b3.z + c3.w*b3.w;
        c0 = p0; c1 = p1; c2 = p2; c3 = p3;
    }
    // epilogue chunk
    {
        float4 b0 = x4[i];      float4 b1 = x4[i + 32];
        float4 b2 = x4[i + 64]; float4 b3 = x4[i + 96];
        acc0 += c0.x*b0.x + c0.y*b0.y + c0.z*b0.z + c0.w*b0.w;
        acc1 += c1.x*b1.x + c1.y*b1.y + c1.z*b1.z + c1.w*b1.w;
        acc2 += c2.x*b2.x + c2.y*b2.y + c2.z*b2.z + c2.w*b2.w;
        acc3 += c3.x*b3.x + c3.y*b3.y + c3.z*b3.z + c3.w*b3.w;
    }
    return (acc0 + acc1) + (acc2 + acc3);
}

__device__ __forceinline__ float warp_reduce(float s) {
    #pragma unroll
    for (int off = 16; off; off >>= 1)
        s += __shfl_xor_sync(0xffffffffu, s, off);
    return s;
}

// ---------------- kernels ----------------

__global__ void flag_kernel(const float* __restrict__ act0,
                            const float* __restrict__ out0) {
    const float* p = (blockIdx.x == 0) ? act0 : out0;
    const int    n = (blockIdx.x == 0) ? NH : NO;
    int any = 0;
    for (int i = threadIdx.x; i < n; i += blockDim.x)
        any |= (p[i] != 0.f);
    any = __syncthreads_or(any);
    if (threadIdx.x == 0) {
        g_flags[blockIdx.x] = any;
        g_flags[2] = 1;
    }
}

// Fused loop-invariant bases for hidden AND output rows in one launch.
// Blocks [0, NH/8): base_h rows. Blocks [NH/8, NH/8+NO/8): base_o rows.
// If activs0 is all-zero, also emits the step-1 result act_a directly.
__global__ void base_fused_kernel(
    const float* __restrict__ W_i2h, const float* __restrict__ W_o2h,
    const float* __restrict__ W_i2o, const float* __restrict__ W_o2o,
    const float* __restrict__ inputs, const float* __restrict__ outputs0,
    const float* __restrict__ h_resp, const float* __restrict__ h_bias,
    const int*   __restrict__ h_ids)
{
    const int warp = (blockIdx.x * blockDim.x + threadIdx.x) >> 5;
    const int lane = threadIdx.x & 31;
    const int out_flag = g_flags[1];

    if (warp < NH) {                    // hidden base row
        const int row = warp;
        float s = warp_dot(W_i2h + (size_t)row * NI, inputs, NI, lane);
        if (out_flag)
            s += warp_dot(W_o2h + (size_t)row * NO, outputs0, NO, lane);
        s = warp_reduce(s);
        if (lane == 0) {
            g_base_h[row] = s;
            if (!g_flags[0]) {          // activs0 == 0 -> step-1 result now
                float pre = h_resp[row] * s + h_bias[row];
                g_act_a[row] = apply_act(pre, h_ids[row]);
            }
        }
    } else {                            // output base row
        const int row = warp - NH;
        if (row >= NO) return;
        float s = warp_dot(W_i2o + (size_t)row * NI, inputs, NI, lane);
        if (out_flag)
            s += warp_dot(W_o2o + (size_t)row * NO, outputs0, NO, lane);
        s = warp_reduce(s);
        if (lane == 0) g_base_o[row] = s;
    }
}

// Step-1 hidden kernel: early-exit if activs0 was all-zero (act_a already
// written by base_fused_kernel); otherwise full GEMV + epilogue.
__global__ void step1_kernel(const float* __restrict__ W,
                             const float* __restrict__ activs0,
                             const float* __restrict__ resp,
                             const float* __restrict__ bias,
                             const int*   __restrict__ ids)
{
    if (!g_flags[0]) return;
    const int row  = (blockIdx.x * blockDim.x + threadIdx.x) >> 5;
    const int lane = threadIdx.x & 31;
    if (row >= NH) return;
    float s = warp_dot(W + (size_t)row * NH, activs0, NH, lane);
    s = warp_reduce(s);
    if (lane == 0) {
        float pre = resp[row] * (g_base_h[row] + s) + bias[row];
        g_act_a[row] = apply_act(pre, ids[row]);
    }
}

// Generic recurrent / output GEMV + activation epilogue.
__global__ void gemv_act_kernel(const float* __restrict__ W,
                                const float* __restrict__ x, int K,
                                const float* __restrict__ base,
                                const float* __restrict__ resp,
                                const float* __restrict__ bias,
                                const int*   __restrict__ ids,
                                float* __restrict__ y, int M)
{
    const int row  = (blockIdx.x * blockDim.x + threadIdx.x) >> 5;
    const int lane = threadIdx.x & 31;
    if (row >= M) return;
    float s = warp_dot(W + (size_t)row * K, x, K, lane);
    s = warp_reduce(s);
    if (lane == 0) {
        float pre = resp[row] * (base[row] + s) + bias[row];
        y[row] = apply_act(pre, ids[row]);
    }
}

// ---------------- launch ----------------
extern "C" void kernel_launch(void* const* d_in, const int* in_sizes, int n_in,
                              void* d_out, int out_size) {
    const float* inputs   = (const float*)d_in[0];
    const float* W_i2h    = (const float*)d_in[1];
    const float* W_h2h    = (const float*)d_in[2];
    const float* W_o2h    = (const float*)d_in[3];
    const float* W_i2o    = (const float*)d_in[4];
    const float* W_h2o    = (const float*)d_in[5];
    const float* W_o2o    = (const float*)d_in[6];
    const float* h_resp   = (const float*)d_in[7];
    const float* h_bias   = (const float*)d_in[8];
    const float* o_resp   = (const float*)d_in[9];
    const float* o_bias   = (const float*)d_in[10];
    const float* activs0  = (const float*)d_in[11];
    const float* outputs0 = (const float*)d_in[12];
    const int*   h_ids    = (const int*)d_in[13];
    const int*   o_ids    = (const int*)d_in[14];
    float* out = (float*)d_out;

    static float *base_h = nullptr, *base_o, *act_a, *act_b;
    if (!base_h) {
        cudaGetSymbolAddress((void**)&base_h, g_base_h);
        cudaGetSymbolAddress((void**)&base_o, g_base_o);
        cudaGetSymbolAddress((void**)&act_a,  g_act_a);
        cudaGetSymbolAddress((void**)&act_b,  g_act_b);
    }

    const int THREADS  = 256;                    // 8 warps = 8 rows / block
    const int BLK_NH   = NH / 8;                 // 1024
    const int BLK_NO   = NO / 8;                 // 256
    const int BLK_BASE = BLK_NH + BLK_NO;        // 1280

    // 0. zero-vector flags
    flag_kernel<<<2, THREADS>>>(activs0, outputs0);

    // 1. all loop-invariant bases in one launch (+ step-1 result if activs0==0)
    base_fused_kernel<<<BLK_BASE, THREADS>>>(W_i2h, W_o2h, W_i2o, W_o2o,
                                             inputs, outputs0,
                                             h_resp, h_bias, h_ids);

    // 2. recurrent steps
    step1_kernel<<<BLK_NH, THREADS>>>(W_h2h, activs0, h_resp, h_bias, h_ids);
    gemv_act_kernel<<<BLK_NH, THREADS>>>(W_h2h, act_a, NH, base_h,
                                         h_resp, h_bias, h_ids, act_b, NH);
    gemv_act_kernel<<<BLK_NH, THREADS>>>(W_h2h, act_b, NH, base_h,
                                         h_resp, h_bias, h_ids, act_a, NH);

    // 3. output layer
    gemv_act_kernel<<<BLK_NO, THREADS>>>(W_h2o, act_a, NH, base_o,
                                         o_resp, o_bias, o_ids, out, NO);
}